// round 2
// baseline (speedup 1.0000x reference)
#include <cuda_runtime.h>
#include <stdint.h>
#include <math.h>

// Problem constants
#define BHALF 4096          // B
#define NROWS 8192          // 2B
#define DDIM  256           // D
#define INV_T (1.0f / 0.07f)

#define NTHREADS 256
#define LDA 36              // padded smem row stride (floats): bank = (4r + c) & 31, conflict-free

// ---------------- scratch (no allocations allowed) ----------------
__device__ float g_zn[NROWS * DDIM];     // normalized rows (tf32-rounded), 8 MB
__device__ float g_negsum[NROWS];
__device__ float g_pos[NROWS];

// ---------------- kernel 1: normalize + tf32 round + zero accumulators ----------------
__global__ void normalize_kernel(const float* __restrict__ z_i,
                                 const float* __restrict__ z_j) {
    int row = blockIdx.x;
    int t = threadIdx.x;

    float x;
    if (row < BHALF) x = z_i[row * DDIM + t];
    else             x = z_j[(row - BHALF) * DDIM + t];

    __shared__ float red[32];
    float ss = x * x;
    #pragma unroll
    for (int o = 16; o > 0; o >>= 1) ss += __shfl_down_sync(0xffffffffu, ss, o);
    if ((t & 31) == 0) red[t >> 5] = ss;
    __syncthreads();
    if (t < 32) {
        float v = (t < (NTHREADS / 32)) ? red[t] : 0.0f;
        #pragma unroll
        for (int o = 4; o > 0; o >>= 1) v += __shfl_down_sync(0xffffffffu, v, o);
        if (t == 0) red[0] = v;
    }
    __syncthreads();

    float inv = 1.0f / fmaxf(sqrtf(red[0]), 1e-12f);
    float zn = x * inv;
    uint32_t tf;
    asm("cvt.rna.tf32.f32 %0, %1;" : "=r"(tf) : "f"(zn));
    g_zn[row * DDIM + t] = __uint_as_float(tf);

    if (t == 0) {
        g_negsum[row] = 0.0f;   // re-zero every launch (graph replays)
        g_pos[row]    = 0.0f;
    }
}

// ---------------- kernel 2: tf32 tensor-core Gram + exp row-sums ----------------
// Block tile 128x128, BK=32. 8 warps: 2 (m) x 4 (n), warp tile 64x32.
// Per warp per k8-step: 4 m-tiles x 4 n-tiles of mma.m16n8k8.
__global__ __launch_bounds__(NTHREADS, 2) void gram_kernel() {
    __shared__ float As[128 * LDA];
    __shared__ float Bs[128 * LDA];
    __shared__ float rowsum[128];

    const int tid  = threadIdx.x;
    const int lane = tid & 31;
    const int g    = lane >> 2;     // groupID (0..7)
    const int tig  = lane & 3;      // thread-in-group (0..3)
    const int warp = tid >> 5;
    const int wm   = (warp >> 2) * 64;   // warp m offset (0,64)
    const int wn   = (warp & 3) * 32;    // warp n offset (0,32,64,96)
    const int mBase = blockIdx.y * 128;
    const int nBase = blockIdx.x * 128;

    float acc[4][4][4] = {};

    for (int k0 = 0; k0 < DDIM; k0 += 32) {
        // cooperative tile load: 128 rows x 32 k, float4 x4 per thread
        #pragma unroll
        for (int it = 0; it < 4; it++) {
            int t  = tid + it * NTHREADS;   // 0..1023
            int r  = t >> 3;                // 0..127
            int kq = t & 7;                 // float4 slot
            float4 a = *reinterpret_cast<const float4*>(
                &g_zn[(mBase + r) * DDIM + k0 + kq * 4]);
            *reinterpret_cast<float4*>(&As[r * LDA + kq * 4]) = a;
            float4 b = *reinterpret_cast<const float4*>(
                &g_zn[(nBase + r) * DDIM + k0 + kq * 4]);
            *reinterpret_cast<float4*>(&Bs[r * LDA + kq * 4]) = b;
        }
        __syncthreads();

        #pragma unroll
        for (int kk = 0; kk < 4; kk++) {
            uint32_t a[4][4];
            #pragma unroll
            for (int mt = 0; mt < 4; mt++) {
                const uint32_t* p = reinterpret_cast<const uint32_t*>(
                    &As[(wm + mt * 16 + g) * LDA + kk * 8 + tig]);
                a[mt][0] = p[0];            // (row g,    col tig)
                a[mt][2] = p[4];            // (row g,    col tig+4)
                a[mt][1] = p[8 * LDA];      // (row g+8,  col tig)
                a[mt][3] = p[8 * LDA + 4];  // (row g+8,  col tig+4)
            }
            #pragma unroll
            for (int nt = 0; nt < 4; nt++) {
                const uint32_t* q = reinterpret_cast<const uint32_t*>(
                    &Bs[(wn + nt * 8 + g) * LDA + kk * 8 + tig]);
                uint32_t b0 = q[0];         // (k tig,   n g)
                uint32_t b1 = q[4];         // (k tig+4, n g)
                #pragma unroll
                for (int mt = 0; mt < 4; mt++) {
                    asm volatile(
                        "mma.sync.aligned.m16n8k8.row.col.f32.tf32.tf32.f32 "
                        "{%0,%1,%2,%3}, {%4,%5,%6,%7}, {%8,%9}, {%0,%1,%2,%3};"
                        : "+f"(acc[mt][nt][0]), "+f"(acc[mt][nt][1]),
                          "+f"(acc[mt][nt][2]), "+f"(acc[mt][nt][3])
                        : "r"(a[mt][0]), "r"(a[mt][1]),
                          "r"(a[mt][2]), "r"(a[mt][3]),
                          "r"(b0), "r"(b1));
                }
            }
        }
        __syncthreads();
    }

    // ---- epilogue: exp + per-row sum; capture pos; skip diagonal ----
    if (tid < 128) rowsum[tid] = 0.0f;
    __syncthreads();

    float rs[4][2] = {};   // per m-tile, per row-half
    #pragma unroll
    for (int mt = 0; mt < 4; mt++) {
        int r0 = mBase + wm + mt * 16 + g;
        int r1 = r0 + 8;
        #pragma unroll
        for (int nt = 0; nt < 4; nt++) {
            int c0 = nBase + wn + nt * 8 + 2 * tig;
            int c1 = c0 + 1;
            // c layout: [0]=(r0,c0) [1]=(r0,c1) [2]=(r1,c0) [3]=(r1,c1)
            {
                float s = acc[mt][nt][0] * INV_T;
                if (c0 == (r0 ^ BHALF)) g_pos[r0] = s;
                if (c0 != r0) rs[mt][0] += __expf(s);
            }
            {
                float s = acc[mt][nt][1] * INV_T;
                if (c1 == (r0 ^ BHALF)) g_pos[r0] = s;
                if (c1 != r0) rs[mt][0] += __expf(s);
            }
            {
                float s = acc[mt][nt][2] * INV_T;
                if (c0 == (r1 ^ BHALF)) g_pos[r1] = s;
                if (c0 != r1) rs[mt][1] += __expf(s);
            }
            {
                float s = acc[mt][nt][3] * INV_T;
                if (c1 == (r1 ^ BHALF)) g_pos[r1] = s;
                if (c1 != r1) rs[mt][1] += __expf(s);
            }
        }
        atomicAdd(&rowsum[wm + mt * 16 + g],     rs[mt][0]);
        atomicAdd(&rowsum[wm + mt * 16 + g + 8], rs[mt][1]);
    }
    __syncthreads();
    if (tid < 128) atomicAdd(&g_negsum[mBase + tid], rowsum[tid]);
}

// ---------------- kernel 3: finalize ----------------
__global__ void finalize_kernel(float* __restrict__ out) {
    __shared__ float red[32];
    int t = threadIdx.x;
    float acc = 0.0f;
    for (int i = t; i < NROWS; i += NTHREADS)
        acc += logf(g_negsum[i]) - g_pos[i];
    #pragma unroll
    for (int o = 16; o > 0; o >>= 1) acc += __shfl_down_sync(0xffffffffu, acc, o);
    if ((t & 31) == 0) red[t >> 5] = acc;
    __syncthreads();
    if (t < 32) {
        float v = (t < (NTHREADS / 32)) ? red[t] : 0.0f;
        #pragma unroll
        for (int o = 4; o > 0; o >>= 1) v += __shfl_down_sync(0xffffffffu, v, o);
        if (t == 0) out[0] = v / (float)NROWS;
    }
}

extern "C" void kernel_launch(void* const* d_in, const int* in_sizes, int n_in,
                              void* d_out, int out_size) {
    const float* z_i = (const float*)d_in[0];
    const float* z_j = (const float*)d_in[1];
    float* out = (float*)d_out;

    normalize_kernel<<<NROWS, NTHREADS>>>(z_i, z_j);
    dim3 grid(NROWS / 128, NROWS / 128);
    gram_kernel<<<grid, NTHREADS>>>();
    finalize_kernel<<<1, NTHREADS>>>(out);
}

// round 3
// speedup vs baseline: 1.5010x; 1.5010x over previous
#include <cuda_runtime.h>
#include <stdint.h>
#include <math.h>

// Problem constants
#define BHALF 4096          // B
#define NROWS 8192          // 2B
#define DDIM  256           // D
#define INV_T (1.0f / 0.07f)

#define NTHREADS 256
#define LDA 36              // padded smem row stride (floats): conflict-free fragment loads
#define NBLK 64             // NROWS / 128
#define NPAIRS (NBLK * (NBLK + 1) / 2)   // 2080 upper-triangular block tiles

// ---------------- scratch (no allocations allowed) ----------------
__device__ float g_zn[NROWS * DDIM];     // normalized rows (tf32-rounded), 8 MB
__device__ float g_negsum[NROWS];
__device__ float g_pos[NROWS];

// ---------------- kernel 1: normalize + tf32 round + zero accumulators ----------------
__global__ void normalize_kernel(const float* __restrict__ z_i,
                                 const float* __restrict__ z_j) {
    int row = blockIdx.x;
    int t = threadIdx.x;

    float x;
    if (row < BHALF) x = z_i[row * DDIM + t];
    else             x = z_j[(row - BHALF) * DDIM + t];

    __shared__ float red[32];
    float ss = x * x;
    #pragma unroll
    for (int o = 16; o > 0; o >>= 1) ss += __shfl_down_sync(0xffffffffu, ss, o);
    if ((t & 31) == 0) red[t >> 5] = ss;
    __syncthreads();
    if (t < 32) {
        float v = (t < (NTHREADS / 32)) ? red[t] : 0.0f;
        #pragma unroll
        for (int o = 4; o > 0; o >>= 1) v += __shfl_down_sync(0xffffffffu, v, o);
        if (t == 0) red[0] = v;
    }
    __syncthreads();

    float inv = 1.0f / fmaxf(sqrtf(red[0]), 1e-12f);
    float zn = x * inv;
    uint32_t tf;
    asm("cvt.rna.tf32.f32 %0, %1;" : "=r"(tf) : "f"(zn));
    g_zn[row * DDIM + t] = __uint_as_float(tf);

    if (t == 0) {
        g_negsum[row] = 0.0f;   // re-zero every launch (graph replays)
        g_pos[row]    = 0.0f;
    }
}

// linear upper-tri index -> (bi, bj), bi <= bj
// Start(bi) = bi*NBLK - bi*(bi-1)/2
__device__ __forceinline__ int tri_start(int bi) {
    return bi * NBLK - (bi * (bi - 1)) / 2;
}

// ---------------- kernel 2: symmetric tf32 Gram + exp row/col sums ----------------
// Upper-triangular block tiles only. Block tile 128x128, BK=32.
// 8 warps: 2 (m) x 4 (n), warp tile 64x32; mma.m16n8k8 tf32.
__global__ __launch_bounds__(NTHREADS, 2) void gram_kernel() {
    __shared__ float As[128 * LDA];
    __shared__ float Bs[128 * LDA];
    __shared__ float rowsum[128];
    __shared__ float colsum[128];

    // decode upper-triangular pair
    int p = blockIdx.x;
    int bi = (int)(64.5f - sqrtf(64.5f * 64.5f - 2.0f * (float)p));
    if (bi < 0) bi = 0;
    if (bi > NBLK - 1) bi = NBLK - 1;
    while (bi + 1 <= NBLK - 1 && tri_start(bi + 1) <= p) bi++;
    while (tri_start(bi) > p) bi--;
    int bj = bi + (p - tri_start(bi));
    const bool diag = (bi == bj);

    const int tid  = threadIdx.x;
    const int lane = tid & 31;
    const int g    = lane >> 2;     // groupID (0..7)
    const int tig  = lane & 3;      // thread-in-group (0..3)
    const int warp = tid >> 5;
    const int wm   = (warp >> 2) * 64;   // warp m offset (0,64)
    const int wn   = (warp & 3) * 32;    // warp n offset (0,32,64,96)
    const int mBase = bi * 128;
    const int nBase = bj * 128;

    float acc[4][4][4] = {};

    for (int k0 = 0; k0 < DDIM; k0 += 32) {
        #pragma unroll
        for (int it = 0; it < 4; it++) {
            int t  = tid + it * NTHREADS;   // 0..1023
            int r  = t >> 3;                // 0..127
            int kq = t & 7;                 // float4 slot
            float4 a = *reinterpret_cast<const float4*>(
                &g_zn[(mBase + r) * DDIM + k0 + kq * 4]);
            *reinterpret_cast<float4*>(&As[r * LDA + kq * 4]) = a;
            float4 b = *reinterpret_cast<const float4*>(
                &g_zn[(nBase + r) * DDIM + k0 + kq * 4]);
            *reinterpret_cast<float4*>(&Bs[r * LDA + kq * 4]) = b;
        }
        __syncthreads();

        #pragma unroll
        for (int kk = 0; kk < 4; kk++) {
            uint32_t a[4][4];
            #pragma unroll
            for (int mt = 0; mt < 4; mt++) {
                const uint32_t* pA = reinterpret_cast<const uint32_t*>(
                    &As[(wm + mt * 16 + g) * LDA + kk * 8 + tig]);
                a[mt][0] = pA[0];
                a[mt][2] = pA[4];
                a[mt][1] = pA[8 * LDA];
                a[mt][3] = pA[8 * LDA + 4];
            }
            #pragma unroll
            for (int nt = 0; nt < 4; nt++) {
                const uint32_t* q = reinterpret_cast<const uint32_t*>(
                    &Bs[(wn + nt * 8 + g) * LDA + kk * 8 + tig]);
                uint32_t b0 = q[0];
                uint32_t b1 = q[4];
                #pragma unroll
                for (int mt = 0; mt < 4; mt++) {
                    asm volatile(
                        "mma.sync.aligned.m16n8k8.row.col.f32.tf32.tf32.f32 "
                        "{%0,%1,%2,%3}, {%4,%5,%6,%7}, {%8,%9}, {%0,%1,%2,%3};"
                        : "+f"(acc[mt][nt][0]), "+f"(acc[mt][nt][1]),
                          "+f"(acc[mt][nt][2]), "+f"(acc[mt][nt][3])
                        : "r"(a[mt][0]), "r"(a[mt][1]),
                          "r"(a[mt][2]), "r"(a[mt][3]),
                          "r"(b0), "r"(b1));
                }
            }
        }
        __syncthreads();
    }

    // ---- epilogue ----
    if (tid < 128) { rowsum[tid] = 0.0f; colsum[tid] = 0.0f; }
    __syncthreads();

    float rs[4][2] = {};        // per m-tile, per row-half (row sums)
    float cs[4][2] = {};        // per n-tile, per col (col sums, off-diag only)

    #pragma unroll
    for (int mt = 0; mt < 4; mt++) {
        int r0 = mBase + wm + mt * 16 + g;
        int r1 = r0 + 8;
        #pragma unroll
        for (int nt = 0; nt < 4; nt++) {
            int c0 = nBase + wn + nt * 8 + 2 * tig;
            int c1 = c0 + 1;
            float s00 = acc[mt][nt][0] * INV_T;   // (r0,c0)
            float s01 = acc[mt][nt][1] * INV_T;   // (r0,c1)
            float s10 = acc[mt][nt][2] * INV_T;   // (r1,c0)
            float s11 = acc[mt][nt][3] * INV_T;   // (r1,c1)
            float e00 = __expf(s00);
            float e01 = __expf(s01);
            float e10 = __expf(s10);
            float e11 = __expf(s11);
            if (diag) {
                // rows == cols range; count each element once for its row, skip diagonal
                if (c0 != r0) rs[mt][0] += e00;
                if (c1 != r0) rs[mt][0] += e01;
                if (c0 != r1) rs[mt][1] += e10;
                if (c1 != r1) rs[mt][1] += e11;
            } else {
                rs[mt][0] += e00 + e01;
                rs[mt][1] += e10 + e11;
                cs[nt][0] += e00 + e10;
                cs[nt][1] += e01 + e11;
                if (c0 == (r0 ^ BHALF)) { g_pos[r0] = s00; g_pos[c0] = s00; }
                if (c1 == (r0 ^ BHALF)) { g_pos[r0] = s01; g_pos[c1] = s01; }
                if (c0 == (r1 ^ BHALF)) { g_pos[r1] = s10; g_pos[c0] = s10; }
                if (c1 == (r1 ^ BHALF)) { g_pos[r1] = s11; g_pos[c1] = s11; }
            }
        }
        atomicAdd(&rowsum[wm + mt * 16 + g],     rs[mt][0]);
        atomicAdd(&rowsum[wm + mt * 16 + g + 8], rs[mt][1]);
    }
    if (!diag) {
        #pragma unroll
        for (int nt = 0; nt < 4; nt++) {
            atomicAdd(&colsum[wn + nt * 8 + 2 * tig],     cs[nt][0]);
            atomicAdd(&colsum[wn + nt * 8 + 2 * tig + 1], cs[nt][1]);
        }
    }
    __syncthreads();
    if (tid < 128) {
        atomicAdd(&g_negsum[mBase + tid], rowsum[tid]);
        if (!diag) atomicAdd(&g_negsum[nBase + tid], colsum[tid]);
    }
}

// ---------------- kernel 3: finalize ----------------
__global__ void finalize_kernel(float* __restrict__ out) {
    __shared__ float red[32];
    int t = threadIdx.x;
    float acc = 0.0f;
    for (int i = t; i < NROWS; i += NTHREADS)
        acc += logf(g_negsum[i]) - g_pos[i];
    #pragma unroll
    for (int o = 16; o > 0; o >>= 1) acc += __shfl_down_sync(0xffffffffu, acc, o);
    if ((t & 31) == 0) red[t >> 5] = acc;
    __syncthreads();
    if (t < 32) {
        float v = (t < (NTHREADS / 32)) ? red[t] : 0.0f;
        #pragma unroll
        for (int o = 4; o > 0; o >>= 1) v += __shfl_down_sync(0xffffffffu, v, o);
        if (t == 0) out[0] = v / (float)NROWS;
    }
}

extern "C" void kernel_launch(void* const* d_in, const int* in_sizes, int n_in,
                              void* d_out, int out_size) {
    const float* z_i = (const float*)d_in[0];
    const float* z_j = (const float*)d_in[1];
    float* out = (float*)d_out;

    normalize_kernel<<<NROWS, NTHREADS>>>(z_i, z_j);
    gram_kernel<<<NPAIRS, NTHREADS>>>();
    finalize_kernel<<<1, NTHREADS>>>(out);
}

// round 6
// speedup vs baseline: 2.0916x; 1.3935x over previous
#include <cuda_runtime.h>
#include <cuda_bf16.h>
#include <stdint.h>
#include <math.h>

// Problem constants
#define BHALF 4096          // B
#define NROWS 8192          // 2B
#define DDIM  256           // D
#define INV_T (1.0f / 0.07f)
#define LOG2E 1.4426950408889634f
#define LN2   0.6931471805599453f
// zn pre-scale so MMA acc == s*log2e directly: sqrt(INV_T * LOG2E)
#define PRESCALE 4.539801877979346f

#define NTHREADS 256
#define LDW 36              // padded smem row stride in 32-bit words (72 bf16)
#define NBLK 64             // NROWS / 128
#define NPAIRS (NBLK * (NBLK + 1) / 2)   // 2080 upper-triangular block tiles

// ---------------- scratch (no allocations allowed) ----------------
__device__ __nv_bfloat16 g_zn[NROWS * DDIM];   // prescaled normalized rows, 4 MB
__device__ float g_negsum[NROWS];
__device__ float g_pos[NROWS];

__device__ __forceinline__ float ex2(float x) {
    float y;
    asm("ex2.approx.f32 %0, %1;" : "=f"(y) : "f"(x));
    return y;
}

// ---------------- kernel 1: normalize + prescale + bf16 + zero accumulators ----------------
__global__ void normalize_kernel(const float* __restrict__ z_i,
                                 const float* __restrict__ z_j) {
    int row = blockIdx.x;
    int t = threadIdx.x;

    float x;
    if (row < BHALF) x = z_i[row * DDIM + t];
    else             x = z_j[(row - BHALF) * DDIM + t];

    __shared__ float red[32];
    float ss = x * x;
    #pragma unroll
    for (int o = 16; o > 0; o >>= 1) ss += __shfl_down_sync(0xffffffffu, ss, o);
    if ((t & 31) == 0) red[t >> 5] = ss;
    __syncthreads();
    if (t < 32) {
        float v = (t < (NTHREADS / 32)) ? red[t] : 0.0f;
        #pragma unroll
        for (int o = 4; o > 0; o >>= 1) v += __shfl_down_sync(0xffffffffu, v, o);
        if (t == 0) red[0] = v;
    }
    __syncthreads();

    float inv = PRESCALE / fmaxf(sqrtf(red[0]), 1e-12f);
    g_zn[row * DDIM + t] = __float2bfloat16(x * inv);

    if (t == 0) {
        g_negsum[row] = 0.0f;   // re-zero every launch (graph replays)
        g_pos[row]    = 0.0f;
    }
}

// linear upper-tri index -> (bi, bj), bi <= bj
__device__ __forceinline__ int tri_start(int bi) {
    return bi * NBLK - (bi * (bi - 1)) / 2;
}

// ---------------- kernel 2: symmetric bf16 Gram + ex2 row/col sums ----------------
// Upper-triangular block tiles. Block tile 128x128, K chunk = 64 bf16.
// 8 warps: 2 (m) x 4 (n), warp tile 64x32; mma.m16n8k16 bf16.
// acc holds s*log2e directly (inputs prescaled), epilogue = ex2 + adds.
__global__ __launch_bounds__(NTHREADS, 2) void gram_kernel() {
    __shared__ __align__(16) uint32_t As[128 * LDW];
    __shared__ __align__(16) uint32_t Bs[128 * LDW];
    __shared__ float rowsum[128];
    __shared__ float colsum[128];

    // decode upper-triangular pair
    int p = blockIdx.x;
    int bi = (int)(64.5f - sqrtf(64.5f * 64.5f - 2.0f * (float)p));
    if (bi < 0) bi = 0;
    if (bi > NBLK - 1) bi = NBLK - 1;
    while (bi + 1 <= NBLK - 1 && tri_start(bi + 1) <= p) bi++;
    while (tri_start(bi) > p) bi--;
    int bj = bi + (p - tri_start(bi));
    const bool diag = (bi == bj);
    const bool hasPos = (bj - bi == 32);   // partner offset 4096 = 32 block tiles

    const int tid  = threadIdx.x;
    const int lane = tid & 31;
    const int g    = lane >> 2;     // groupID (0..7)
    const int tig  = lane & 3;      // thread-in-group (0..3)
    const int warp = tid >> 5;
    const int wm   = (warp >> 2) * 64;   // warp m offset (0,64)
    const int wn   = (warp & 3) * 32;    // warp n offset (0,32,64,96)
    const int mBase = bi * 128;
    const int nBase = bj * 128;

    float acc[4][4][4] = {};

    for (int k0 = 0; k0 < DDIM; k0 += 64) {
        // load 128 rows x 64 bf16 per operand: 1024 float4 each, 4/thread
        #pragma unroll
        for (int it = 0; it < 4; it++) {
            int t = tid + it * NTHREADS;   // 0..1023
            int r = t >> 3;                // 0..127
            int q = t & 7;                 // float4 slot (8 bf16 each)
            float4 a = *reinterpret_cast<const float4*>(
                &g_zn[(mBase + r) * DDIM + k0 + q * 8]);
            *reinterpret_cast<float4*>(&As[r * LDW + q * 4]) = a;
            float4 b = *reinterpret_cast<const float4*>(
                &g_zn[(nBase + r) * DDIM + k0 + q * 8]);
            *reinterpret_cast<float4*>(&Bs[r * LDW + q * 4]) = b;
        }
        __syncthreads();

        #pragma unroll
        for (int kk = 0; kk < 4; kk++) {       // k16 steps within the 64-chunk
            uint32_t a[4][4];
            #pragma unroll
            for (int mt = 0; mt < 4; mt++) {
                const uint32_t* pA = &As[(wm + mt * 16 + g) * LDW + kk * 8 + tig];
                a[mt][0] = pA[0];            // (row g,   k 2tig..2tig+1)
                a[mt][2] = pA[4];            // (row g,   k 2tig+8..+9)
                a[mt][1] = pA[8 * LDW];      // (row g+8, k 2tig..)
                a[mt][3] = pA[8 * LDW + 4];  // (row g+8, k 2tig+8..)
            }
            #pragma unroll
            for (int nt = 0; nt < 4; nt++) {
                const uint32_t* q = &Bs[(wn + nt * 8 + g) * LDW + kk * 8 + tig];
                uint32_t b0 = q[0];
                uint32_t b1 = q[4];
                #pragma unroll
                for (int mt = 0; mt < 4; mt++) {
                    asm volatile(
                        "mma.sync.aligned.m16n8k16.row.col.f32.bf16.bf16.f32 "
                        "{%0,%1,%2,%3}, {%4,%5,%6,%7}, {%8,%9}, {%0,%1,%2,%3};"
                        : "+f"(acc[mt][nt][0]), "+f"(acc[mt][nt][1]),
                          "+f"(acc[mt][nt][2]), "+f"(acc[mt][nt][3])
                        : "r"(a[mt][0]), "r"(a[mt][1]),
                          "r"(a[mt][2]), "r"(a[mt][3]),
                          "r"(b0), "r"(b1));
                }
            }
        }
        __syncthreads();
    }

    // ---- epilogue: acc is already s*log2e -> ex2 + row/col sums ----
    if (tid < 128) { rowsum[tid] = 0.0f; colsum[tid] = 0.0f; }
    __syncthreads();

    float rs[4][2] = {};        // per m-tile: rows g, g+8
    float cs[4][2] = {};        // per n-tile: cols 2tig, 2tig+1

    #pragma unroll
    for (int mt = 0; mt < 4; mt++) {
        int r0 = mBase + wm + mt * 16 + g;
        int r1 = r0 + 8;
        #pragma unroll
        for (int nt = 0; nt < 4; nt++) {
            int c0 = nBase + wn + nt * 8 + 2 * tig;
            int c1 = c0 + 1;
            float e0 = ex2(acc[mt][nt][0]);   // (r0,c0)
            float e1 = ex2(acc[mt][nt][1]);   // (r0,c1)
            float e2 = ex2(acc[mt][nt][2]);   // (r1,c0)
            float e3 = ex2(acc[mt][nt][3]);   // (r1,c1)
            if (diag) {
                if (c0 != r0) rs[mt][0] += e0;
                if (c1 != r0) rs[mt][0] += e1;
                if (c0 != r1) rs[mt][1] += e2;
                if (c1 != r1) rs[mt][1] += e3;
            } else {
                rs[mt][0] += e0 + e1;
                rs[mt][1] += e2 + e3;
                cs[nt][0] += e0 + e2;
                cs[nt][1] += e1 + e3;
                if (hasPos) {
                    if (c0 == (r0 ^ BHALF)) { float s = acc[mt][nt][0] * LN2; g_pos[r0] = s; g_pos[c0] = s; }
                    if (c1 == (r0 ^ BHALF)) { float s = acc[mt][nt][1] * LN2; g_pos[r0] = s; g_pos[c1] = s; }
                    if (c0 == (r1 ^ BHALF)) { float s = acc[mt][nt][2] * LN2; g_pos[r1] = s; g_pos[c0] = s; }
                    if (c1 == (r1 ^ BHALF)) { float s = acc[mt][nt][3] * LN2; g_pos[r1] = s; g_pos[c1] = s; }
                }
            }
        }
        atomicAdd(&rowsum[wm + mt * 16 + g],     rs[mt][0]);
        atomicAdd(&rowsum[wm + mt * 16 + g + 8], rs[mt][1]);
    }
    if (!diag) {
        #pragma unroll
        for (int nt = 0; nt < 4; nt++) {
            atomicAdd(&colsum[wn + nt * 8 + 2 * tig],     cs[nt][0]);
            atomicAdd(&colsum[wn + nt * 8 + 2 * tig + 1], cs[nt][1]);
        }
    }
    __syncthreads();
    if (tid < 128) {
        atomicAdd(&g_negsum[mBase + tid], rowsum[tid]);
        if (!diag) atomicAdd(&g_negsum[nBase + tid], colsum[tid]);
    }
}

// ---------------- kernel 3: finalize ----------------
__global__ void finalize_kernel(float* __restrict__ out) {
    __shared__ float red[32];
    int t = threadIdx.x;
    float acc = 0.0f;
    for (int i = t; i < NROWS; i += NTHREADS)
        acc += logf(g_negsum[i]) - g_pos[i];
    #pragma unroll
    for (int o = 16; o > 0; o >>= 1) acc += __shfl_down_sync(0xffffffffu, acc, o);
    if ((t & 31) == 0) red[t >> 5] = acc;
    __syncthreads();
    if (t < 32) {
        float v = (t < (NTHREADS / 32)) ? red[t] : 0.0f;
        #pragma unroll
        for (int o = 4; o > 0; o >>= 1) v += __shfl_down_sync(0xffffffffu, v, o);
        if (t == 0) out[0] = v / (float)NROWS;
    }
}

extern "C" void kernel_launch(void* const* d_in, const int* in_sizes, int n_in,
                              void* d_out, int out_size) {
    const float* z_i = (const float*)d_in[0];
    const float* z_j = (const float*)d_in[1];
    float* out = (float*)d_out;

    normalize_kernel<<<NROWS, NTHREADS>>>(z_i, z_j);
    gram_kernel<<<NPAIRS, NTHREADS>>>();
    finalize_kernel<<<1, NTHREADS>>>(out);
}

// round 13
// speedup vs baseline: 2.1357x; 1.0211x over previous
#include <cuda_runtime.h>
#include <cuda_fp16.h>
#include <stdint.h>
#include <math.h>

// Problem constants
#define BHALF 4096          // B
#define NROWS 8192          // 2B
#define DDIM  256           // D
#define LN2   0.6931471805599453f
// zn pre-scale so MMA acc == s*log2e directly: sqrt((1/T) * log2(e)), T=0.07
#define PRESCALE 4.539801877979346f

#define NTHREADS 256
#define LDW 36              // padded smem row stride in 32-bit words (72 fp16)
#define NBLK 64             // NROWS / 128
#define NPAIRS (NBLK * (NBLK + 1) / 2)   // 2080 upper-triangular block tiles

// ---------------- scratch (no allocations allowed) ----------------
__device__ __half g_zn[NROWS * DDIM];   // prescaled normalized rows, 4 MB
__device__ float g_negsum[NROWS];
__device__ float g_pos[NROWS];

__device__ __forceinline__ float ex2(float x) {
    float y;
    asm("ex2.approx.f32 %0, %1;" : "=f"(y) : "f"(x));
    return y;
}

// ---------------- kernel 1: normalize + prescale + fp16, warp-per-row ----------------
__global__ void normalize_kernel(const float* __restrict__ z_i,
                                 const float* __restrict__ z_j) {
    int warp = threadIdx.x >> 5, lane = threadIdx.x & 31;
    int row = blockIdx.x * 8 + warp;

    const float* src = (row < BHALF) ? (z_i + (size_t)row * DDIM)
                                     : (z_j + (size_t)(row - BHALF) * DDIM);
    float4 f0 = reinterpret_cast<const float4*>(src)[lane * 2];
    float4 f1 = reinterpret_cast<const float4*>(src)[lane * 2 + 1];
    float ss = f0.x*f0.x + f0.y*f0.y + f0.z*f0.z + f0.w*f0.w
             + f1.x*f1.x + f1.y*f1.y + f1.z*f1.z + f1.w*f1.w;
    #pragma unroll
    for (int o = 16; o > 0; o >>= 1) ss += __shfl_xor_sync(0xffffffffu, ss, o);

    float inv = PRESCALE / fmaxf(sqrtf(ss), 1e-12f);

    __half2 p0 = __float22half2_rn(make_float2(f0.x * inv, f0.y * inv));
    __half2 p1 = __float22half2_rn(make_float2(f0.z * inv, f0.w * inv));
    __half2 p2 = __float22half2_rn(make_float2(f1.x * inv, f1.y * inv));
    __half2 p3 = __float22half2_rn(make_float2(f1.z * inv, f1.w * inv));
    uint4 u;
    u.x = *reinterpret_cast<uint32_t*>(&p0);
    u.y = *reinterpret_cast<uint32_t*>(&p1);
    u.z = *reinterpret_cast<uint32_t*>(&p2);
    u.w = *reinterpret_cast<uint32_t*>(&p3);
    *reinterpret_cast<uint4*>(&g_zn[(size_t)row * DDIM + lane * 8]) = u;

    if (lane == 0) { g_negsum[row] = 0.0f; g_pos[row] = 0.0f; }
}

// linear upper-tri index -> (bi, bj), bi <= bj
__device__ __forceinline__ int tri_start(int bi) {
    return bi * NBLK - (bi * (bi - 1)) / 2;
}

// ---------------- kernel 2: symmetric fp16 Gram (f16 accum) + ex2 row/col sums ----------------
// Upper-triangular tiles. Block tile 128x128, K chunk = 64 fp16.
// 8 warps: 2 (m) x 4 (n), warp tile 64x32; mma.m16n8k16.f16.f16.f16.f16.
// acc holds s*log2e directly (inputs prescaled), epilogue = ex2 + adds.
__global__ __launch_bounds__(NTHREADS, 2) void gram_kernel() {
    __shared__ __align__(16) uint32_t As[128 * LDW];
    __shared__ __align__(16) uint32_t Bs[128 * LDW];
    __shared__ float rowsum[128];
    __shared__ float colsum[128];

    // decode upper-triangular pair
    int p = blockIdx.x;
    int bi = (int)(64.5f - sqrtf(64.5f * 64.5f - 2.0f * (float)p));
    if (bi < 0) bi = 0;
    if (bi > NBLK - 1) bi = NBLK - 1;
    while (bi + 1 <= NBLK - 1 && tri_start(bi + 1) <= p) bi++;
    while (tri_start(bi) > p) bi--;
    int bj = bi + (p - tri_start(bi));
    const bool diag = (bi == bj);
    const bool hasPos = (bj - bi == 32);   // partner offset 4096 = 32 block tiles

    const int tid  = threadIdx.x;
    const int lane = tid & 31;
    const int g    = lane >> 2;     // groupID (0..7)
    const int tig  = lane & 3;      // thread-in-group (0..3)
    const int warp = tid >> 5;
    const int wm   = (warp >> 2) * 64;   // warp m offset (0,64)
    const int wn   = (warp & 3) * 32;    // warp n offset (0,32,64,96)
    const int mBase = bi * 128;
    const int nBase = bj * 128;

    uint32_t acc[4][4][2] = {};     // f16x2 accumulator pairs, zero-init

    for (int k0 = 0; k0 < DDIM; k0 += 64) {
        // load 128 rows x 64 fp16 per operand: 1024 float4 each, 4/thread
        #pragma unroll
        for (int it = 0; it < 4; it++) {
            int t = tid + it * NTHREADS;   // 0..1023
            int r = t >> 3;                // 0..127
            int q = t & 7;                 // float4 slot (8 fp16 each)
            float4 a = *reinterpret_cast<const float4*>(
                &g_zn[(size_t)(mBase + r) * DDIM + k0 + q * 8]);
            *reinterpret_cast<float4*>(&As[r * LDW + q * 4]) = a;
            float4 b = *reinterpret_cast<const float4*>(
                &g_zn[(size_t)(nBase + r) * DDIM + k0 + q * 8]);
            *reinterpret_cast<float4*>(&Bs[r * LDW + q * 4]) = b;
        }
        __syncthreads();

        #pragma unroll
        for (int kk = 0; kk < 4; kk++) {       // k16 steps within the 64-chunk
            uint32_t a[4][4];
            #pragma unroll
            for (int mt = 0; mt < 4; mt++) {
                const uint32_t* pA = &As[(wm + mt * 16 + g) * LDW + kk * 8 + tig];
                a[mt][0] = pA[0];            // (row g,   k 2tig..2tig+1)
                a[mt][2] = pA[4];            // (row g,   k 2tig+8..+9)
                a[mt][1] = pA[8 * LDW];      // (row g+8, k 2tig..)
                a[mt][3] = pA[8 * LDW + 4];  // (row g+8, k 2tig+8..)
            }
            #pragma unroll
            for (int nt = 0; nt < 4; nt++) {
                const uint32_t* q = &Bs[(wn + nt * 8 + g) * LDW + kk * 8 + tig];
                uint32_t b0 = q[0];
                uint32_t b1 = q[4];
                #pragma unroll
                for (int mt = 0; mt < 4; mt++) {
                    asm volatile(
                        "mma.sync.aligned.m16n8k16.row.col.f16.f16.f16.f16 "
                        "{%0,%1}, {%2,%3,%4,%5}, {%6,%7}, {%0,%1};"
                        : "+r"(acc[mt][nt][0]), "+r"(acc[mt][nt][1])
                        : "r"(a[mt][0]), "r"(a[mt][1]),
                          "r"(a[mt][2]), "r"(a[mt][3]),
                          "r"(b0), "r"(b1));
                }
            }
        }
        __syncthreads();
    }

    // ---- epilogue: acc is s*log2e (f16 pairs) -> ex2 + row/col sums ----
    if (tid < 128) { rowsum[tid] = 0.0f; colsum[tid] = 0.0f; }
    __syncthreads();

    float rs[4][2] = {};        // per m-tile: rows g, g+8
    float cs[4][2] = {};        // per n-tile: cols 2tig, 2tig+1

    #pragma unroll
    for (int mt = 0; mt < 4; mt++) {
        int r0 = mBase + wm + mt * 16 + g;
        int r1 = r0 + 8;
        #pragma unroll
        for (int nt = 0; nt < 4; nt++) {
            int c0 = nBase + wn + nt * 8 + 2 * tig;
            int c1 = c0 + 1;
            float2 v01 = __half22float2(*reinterpret_cast<__half2*>(&acc[mt][nt][0])); // (r0,c0),(r0,c1)
            float2 v23 = __half22float2(*reinterpret_cast<__half2*>(&acc[mt][nt][1])); // (r1,c0),(r1,c1)
            float e0 = ex2(v01.x);
            float e1 = ex2(v01.y);
            float e2 = ex2(v23.x);
            float e3 = ex2(v23.y);
            if (diag) {
                if (c0 != r0) rs[mt][0] += e0;
                if (c1 != r0) rs[mt][0] += e1;
                if (c0 != r1) rs[mt][1] += e2;
                if (c1 != r1) rs[mt][1] += e3;
            } else {
                rs[mt][0] += e0 + e1;
                rs[mt][1] += e2 + e3;
                cs[nt][0] += e0 + e2;
                cs[nt][1] += e1 + e3;
                if (hasPos) {
                    if (c0 == (r0 ^ BHALF)) { float s = v01.x * LN2; g_pos[r0] = s; g_pos[c0] = s; }
                    if (c1 == (r0 ^ BHALF)) { float s = v01.y * LN2; g_pos[r0] = s; g_pos[c1] = s; }
                    if (c0 == (r1 ^ BHALF)) { float s = v23.x * LN2; g_pos[r1] = s; g_pos[c0] = s; }
                    if (c1 == (r1 ^ BHALF)) { float s = v23.y * LN2; g_pos[r1] = s; g_pos[c1] = s; }
                }
            }
        }
        atomicAdd(&rowsum[wm + mt * 16 + g],     rs[mt][0]);
        atomicAdd(&rowsum[wm + mt * 16 + g + 8], rs[mt][1]);
    }
    if (!diag) {
        #pragma unroll
        for (int nt = 0; nt < 4; nt++) {
            atomicAdd(&colsum[wn + nt * 8 + 2 * tig],     cs[nt][0]);
            atomicAdd(&colsum[wn + nt * 8 + 2 * tig + 1], cs[nt][1]);
        }
    }
    __syncthreads();
    if (tid < 128) {
        atomicAdd(&g_negsum[mBase + tid], rowsum[tid]);
        if (!diag) atomicAdd(&g_negsum[nBase + tid], colsum[tid]);
    }
}

// ---------------- kernel 3: finalize ----------------
__global__ void finalize_kernel(float* __restrict__ out) {
    __shared__ float red[32];
    int t = threadIdx.x;
    float acc = 0.0f;
    for (int i = t; i < NROWS; i += NTHREADS)
        acc += logf(g_negsum[i]) - g_pos[i];
    #pragma unroll
    for (int o = 16; o > 0; o >>= 1) acc += __shfl_down_sync(0xffffffffu, acc, o);
    if ((t & 31) == 0) red[t >> 5] = acc;
    __syncthreads();
    if (t < 32) {
        float v = (t < (NTHREADS / 32)) ? red[t] : 0.0f;
        #pragma unroll
        for (int o = 4; o > 0; o >>= 1) v += __shfl_down_sync(0xffffffffu, v, o);
        if (t == 0) out[0] = v / (float)NROWS;
    }
}

extern "C" void kernel_launch(void* const* d_in, const int* in_sizes, int n_in,
                              void* d_out, int out_size) {
    const float* z_i = (const float*)d_in[0];
    const float* z_j = (const float*)d_in[1];
    float* out = (float*)d_out;

    normalize_kernel<<<NROWS / 8, NTHREADS>>>(z_i, z_j);
    gram_kernel<<<NPAIRS, NTHREADS>>>();
    finalize_kernel<<<1, NTHREADS>>>(out);
}